// round 14
// baseline (speedup 1.0000x reference)
#include <cuda_runtime.h>
#include <cuda_bf16.h>
#include <cstdint>

// Problem shape: n=32, m=16, p=1024, d=512
//   task: [32, 16, 1024] f32
//   feat: [32, 1024, 512] f32
//   out : [32, 1024, 512] f32 = feat * mean_m(task)
#define N_DIM 32
#define M_DIM 16
#define P_DIM 1024
#define D_DIM 512

#define ROWS_PER_BLOCK 16                       // 16 rows * 512 f32 = 32KB tile
#define F4_PER_ROW (D_DIM / 4)                  // 128
#define F4_PER_BLOCK (ROWS_PER_BLOCK * F4_PER_ROW)   // 2048 (8 f4/thread)
#define TILE_BYTES (ROWS_PER_BLOCK * D_DIM * 4) // 32768
#define NUM_BLOCKS ((N_DIM * P_DIM) / ROWS_PER_BLOCK) // 2048

// R14: minimal-TMA variant. Loads stay on the proven LDG float4 path (R7,
// 18.2us). Stores go through SMEM -> one 32KB cp.async.bulk per block: the
// TMA engine emits full 128B-line writes from a single request stream,
// bypassing the per-warp STG/L1tex wavefront path. No mbarriers anywhere --
// the only wait is wait_group 0 on t0's own store, so no hang is possible.

__device__ __forceinline__ uint32_t smem_u32(const void* p) {
    return (uint32_t)__cvta_generic_to_shared(p);
}
__device__ __forceinline__ void bulk_store(void* dst, uint32_t src_smem, uint32_t bytes) {
    asm volatile("cp.async.bulk.global.shared::cta.bulk_group [%0], [%1], %2;"
                 :: "l"(dst), "r"(src_smem), "r"(bytes) : "memory");
}

__global__ void __launch_bounds__(256) fused_kernel(const float* __restrict__ task,
                                                    const float4* __restrict__ feat,
                                                    float* __restrict__ out) {
    __shared__ float4 s_tile[F4_PER_BLOCK];     // 32KB staging for the bulk store
    __shared__ float s_scale[ROWS_PER_BLOCK];

    const int t = threadIdx.x;
    const int block_row0 = blockIdx.x * ROWS_PER_BLOCK;   // global row = n*1024 + p

    // ---- Phase 1: per-row mean over m (16 rows x 16 m = 256 loads, 1/thread) ----
    {
        const int row_local = t >> 4;     // 0..15
        const int m         = t & 15;     // 0..15
        const int grow = block_row0 + row_local;
        const int n = grow >> 10;
        const int p = grow & (P_DIM - 1);
        float v = __ldg(&task[((size_t)n * M_DIM + m) * P_DIM + p]);
        #pragma unroll
        for (int off = 8; off; off >>= 1)
            v += __shfl_xor_sync(0xffffffffu, v, off, 16);
        if (m == 0) s_scale[row_local] = v * (1.0f / M_DIM);
    }
    __syncthreads();

    // ---- Phase 2: LDG loads (proven path), scale, stage to SMEM ----
    const size_t base = (size_t)block_row0 * F4_PER_ROW;

    #pragma unroll
    for (int k = 0; k < 4; ++k) {
        const int i0 = (2 * k) * 256 + t;
        const int i1 = (2 * k + 1) * 256 + t;
        float4 a = feat[base + (size_t)i0];
        float4 b = feat[base + (size_t)i1];
        const float sa = s_scale[i0 >> 7];
        const float sb = s_scale[i1 >> 7];
        a.x *= sa; a.y *= sa; a.z *= sa; a.w *= sa;
        b.x *= sb; b.y *= sb; b.z *= sb; b.w *= sb;
        s_tile[i0] = a;
        s_tile[i1] = b;
    }
    __syncthreads();

    // ---- Phase 3: one 32KB TMA bulk store per block ----
    if (t == 0) {
        asm volatile("fence.proxy.async.shared::cta;" ::: "memory");
        bulk_store(out + (size_t)block_row0 * D_DIM, smem_u32(s_tile), TILE_BYTES);
        asm volatile("cp.async.bulk.commit_group;" ::: "memory");
        asm volatile("cp.async.bulk.wait_group 0;" ::: "memory");
    }
}

extern "C" void kernel_launch(void* const* d_in, const int* in_sizes, int n_in,
                              void* d_out, int out_size) {
    const float* task = (const float*)d_in[0];
    const float* feat = (const float*)d_in[1];
    float* out = (float*)d_out;

    fused_kernel<<<NUM_BLOCKS, 256>>>(task, (const float4*)feat, out);
}

// round 15
// speedup vs baseline: 1.3735x; 1.3735x over previous
#include <cuda_runtime.h>
#include <cuda_bf16.h>
#include <cstdint>

// Problem shape (fixed by reference): n=32, m=16, p=1024, d=512
//   task: [32, 16, 1024] f32
//   feat: [32, 1024, 512] f32
//   out : [32, 1024, 512] f32 = feat * mean_m(task)
//
// FINAL (converged): pure-streaming kernel at the HBM wall.
// 128MB logical traffic / 18.2us kernel = 7.03 TB/s effective (~88% of spec).
// Falsified levers (rounds 2-14): occupancy 36-80%, per-thread MLP 1-8,
// all L2 policies (stcs/ldcs/stwt/evict_last+first), 16B vs 32B accesses,
// TMA bulk loads and stores, 512-2048 block grids -- all within noise of or
// worse than this shape. Remaining bench-vs-kernel gap (~3us) is fixed
// per-replay graph overhead (identical across policy variants to 0.15%).
#define N_DIM 32
#define M_DIM 16
#define P_DIM 1024
#define D_DIM 512

#define ROWS_PER_BLOCK 16                       // 16 rows * 128 f4 = 2048 f4/block
#define F4_PER_ROW (D_DIM / 4)                  // 128
#define NUM_BLOCKS ((N_DIM * P_DIM) / ROWS_PER_BLOCK) // 2048 blocks

__global__ void __launch_bounds__(256, 8) fused_kernel(const float* __restrict__ task,
                                                       const float4* __restrict__ feat,
                                                       float4* __restrict__ out) {
    __shared__ float s_scale[ROWS_PER_BLOCK];

    const int t = threadIdx.x;
    const int block_row0 = blockIdx.x * ROWS_PER_BLOCK;   // global row = n*1024 + p

    // ---- Phase 1: per-row mean over m (16 rows x 16 m = 256 loads, 1/thread) ----
    {
        const int row_local = t >> 4;     // 0..15
        const int m         = t & 15;     // 0..15
        const int grow = block_row0 + row_local;
        const int n = grow >> 10;
        const int p = grow & (P_DIM - 1);
        float v = __ldg(&task[((size_t)n * M_DIM + m) * P_DIM + p]);
        #pragma unroll
        for (int off = 8; off; off >>= 1)
            v += __shfl_xor_sync(0xffffffffu, v, off, 16);
        if (m == 0) s_scale[row_local] = v * (1.0f / M_DIM);
    }
    __syncthreads();

    // ---- Phase 2: 2048 f4/block = 8 f4/thread, as 4 pairs (ILP 2, low regs) ----
    const size_t base = (size_t)block_row0 * F4_PER_ROW;

    #pragma unroll
    for (int k = 0; k < 4; ++k) {
        const int i0 = (2 * k) * 256 + t;
        const int i1 = (2 * k + 1) * 256 + t;
        float4 a = feat[base + (size_t)i0];
        float4 b = feat[base + (size_t)i1];
        const float sa = s_scale[i0 >> 7];
        const float sb = s_scale[i1 >> 7];
        a.x *= sa; a.y *= sa; a.z *= sa; a.w *= sa;
        b.x *= sb; b.y *= sb; b.z *= sb; b.w *= sb;
        // Evict-first streaming stores: best measured steady-state behavior
        // (bench 23.3 -> 21.2 vs default stores).
        __stcs(&out[base + (size_t)i0], a);
        __stcs(&out[base + (size_t)i1], b);
    }
}

extern "C" void kernel_launch(void* const* d_in, const int* in_sizes, int n_in,
                              void* d_out, int out_size) {
    const float* task = (const float*)d_in[0];
    const float* feat = (const float*)d_in[1];
    float* out = (float*)d_out;

    fused_kernel<<<NUM_BLOCKS, 256>>>(task, (const float4*)feat, (float4*)out);
}

// round 17
// speedup vs baseline: 1.5405x; 1.1216x over previous
#include <cuda_runtime.h>
#include <cuda_bf16.h>
#include <cstdint>

// Problem shape (fixed by reference): n=32, m=16, p=1024, d=512
//   task: [32, 16, 1024] f32
//   feat: [32, 1024, 512] f32
//   out : [32, 1024, 512] f32 = feat * mean_m(task)
//
// R17 (= R16 resubmitted after infra failure): wave-quantization fix on the
// converged R7/R15 shape. 2048 blocks @ 8 CTA/SM = 1184 slots -> 1.73 waves
// (tail + 1 wave transition). Here: 1024 blocks, each processing 2
// consecutive 16-row tiles with the identical body -> exactly ONE perfectly
// balanced wave. Everything else unchanged (proven: ILP-2 float4 pairs,
// __stcs stores, ~31 regs, occ ~78%).
#define N_DIM 32
#define M_DIM 16
#define P_DIM 1024
#define D_DIM 512

#define ROWS_PER_TILE 16
#define F4_PER_ROW (D_DIM / 4)                   // 128
#define TILES_PER_BLOCK 2
#define NUM_BLOCKS ((N_DIM * P_DIM) / (ROWS_PER_TILE * TILES_PER_BLOCK)) // 1024

__global__ void __launch_bounds__(256, 8) fused_kernel(const float* __restrict__ task,
                                                       const float4* __restrict__ feat,
                                                       float4* __restrict__ out) {
    __shared__ float s_scale[ROWS_PER_TILE];

    const int t = threadIdx.x;

    #pragma unroll
    for (int tile = 0; tile < TILES_PER_BLOCK; ++tile) {
        const int tile_row0 = (blockIdx.x * TILES_PER_BLOCK + tile) * ROWS_PER_TILE;

        // ---- Phase 1: per-row mean over m (16 rows x 16 m, 1 load/thread) ----
        {
            const int row_local = t >> 4;     // 0..15
            const int m         = t & 15;     // 0..15
            const int grow = tile_row0 + row_local;
            const int n = grow >> 10;
            const int p = grow & (P_DIM - 1);
            float v = __ldg(&task[((size_t)n * M_DIM + m) * P_DIM + p]);
            #pragma unroll
            for (int off = 8; off; off >>= 1)
                v += __shfl_xor_sync(0xffffffffu, v, off, 16);
            if (m == 0) s_scale[row_local] = v * (1.0f / M_DIM);
        }
        __syncthreads();

        // ---- Phase 2: 2048 f4/tile = 8 f4/thread, 4 ILP-2 pairs ----
        const size_t base = (size_t)tile_row0 * F4_PER_ROW;

        #pragma unroll
        for (int k = 0; k < 4; ++k) {
            const int i0 = (2 * k) * 256 + t;
            const int i1 = (2 * k + 1) * 256 + t;
            float4 a = feat[base + (size_t)i0];
            float4 b = feat[base + (size_t)i1];
            const float sa = s_scale[i0 >> 7];
            const float sb = s_scale[i1 >> 7];
            a.x *= sa; a.y *= sa; a.z *= sa; a.w *= sa;
            b.x *= sb; b.y *= sb; b.z *= sb; b.w *= sb;
            __stcs(&out[base + (size_t)i0], a);
            __stcs(&out[base + (size_t)i1], b);
        }

        if (tile + 1 < TILES_PER_BLOCK)
            __syncthreads();   // protect s_scale before next tile overwrites it
    }
}

extern "C" void kernel_launch(void* const* d_in, const int* in_sizes, int n_in,
                              void* d_out, int out_size) {
    const float* task = (const float*)d_in[0];
    const float* feat = (const float*)d_in[1];
    float* out = (float*)d_out;

    fused_kernel<<<NUM_BLOCKS, 256>>>(task, (const float4*)feat, (float4*)out);
}